// round 13
// baseline (speedup 1.0000x reference)
#include <cuda_runtime.h>

#define BN 64
#define CN 32
#define HN 80
#define WN 80
#define LN 6400
#define HEADSN 8
#define NCH 25
#define CHK 256
#define INV_PI 0.31830988618379067f

typedef unsigned long long u64;

__device__ __forceinline__ u64 pk2(float lo, float hi) {
    u64 r; asm("mov.b64 %0,{%1,%2};" : "=l"(r) : "f"(lo), "f"(hi)); return r;
}
__device__ __forceinline__ void upk2(u64 a, float& lo, float& hi) {
    asm("mov.b64 {%0,%1},%2;" : "=f"(lo), "=f"(hi) : "l"(a));
}
__device__ __forceinline__ u64 fma2_(u64 a, u64 b, u64 c) {
    u64 d; asm("fma.rn.f32x2 %0,%1,%2,%3;" : "=l"(d) : "l"(a), "l"(b), "l"(c)); return d;
}
__device__ __forceinline__ u64 add2_(u64 a, u64 b) {
    u64 d; asm("add.rn.f32x2 %0,%1,%2;" : "=l"(d) : "l"(a), "l"(b)); return d;
}
__device__ __forceinline__ u64 mul2_(u64 a, u64 b) {
    u64 d; asm("mul.rn.f32x2 %0,%1,%2;" : "=l"(d) : "l"(a), "l"(b)); return d;
}

// ---------------- device scratch ----------------
static __device__ float g_vbuf[(size_t)BN * LN * CN];
static __device__ float g_f1[(size_t)BN * CN * LN];
static __device__ float g_f2[(size_t)BN * CN * LN];
static __device__ float g_part_la[BN * NCH * HEADSN * 16];
static __device__ float g_part_x[BN * NCH * HEADSN * 24];
static __device__ float g_pf_sum[2 * BN * NCH * 32];
static __device__ float g_pf_max[2 * BN * NCH * 32];
static __device__ float g_s1[BN * CN * CN];
static __device__ float g_s2[BN * CN * CN];
static __device__ float g_pooled1[BN * 2 * LN];
static __device__ float g_pooled2[BN * 2 * LN];
static __device__ float g_y2a[BN * LN];
static __device__ float g_y2b[BN * LN];
static __device__ float g_gstat[BN * 2 * 2];

// ---------------- K1: LA pass1 (R8-proven, unchanged) ----------------
__global__ __launch_bounds__(128) void k_la_pass1(const float* __restrict__ rgb,
                                                  const float* __restrict__ qkvw) {
    __shared__ __align__(16) u64 wdup[64 * 32];
    __shared__ float accsh[4][4][HEADSN][16];
    const int b = blockIdx.y, ch = blockIdx.x, tid = threadIdx.x;
    const int warp = tid >> 5, lane = tid & 31;
    for (int i = tid; i < 64 * 32; i += 128) { float w = qkvw[32 * 32 + i]; wdup[i] = pk2(w, w); }
    __syncthreads();
    const int l0 = ch * CHK + 2 * tid;
    const float* xr = rgb + (size_t)b * CN * LN;
    u64 xp[32];
#pragma unroll
    for (int c = 0; c < 32; c++) xp[c] = *(const u64*)(xr + (size_t)c * LN + l0);
    float* vg0 = g_vbuf + ((size_t)b * LN + l0) * 32;
#pragma unroll
    for (int h = 0; h < HEADSN; h++) {
        u64 kp[4], vp[4];
#pragma unroll
        for (int d = 0; d < 4; d++) {
            const ulonglong2* wk2 = (const ulonglong2*)&wdup[(h * 4 + d) * 32];
            const ulonglong2* wv2 = (const ulonglong2*)&wdup[(32 + h * 4 + d) * 32];
            u64 a0 = 0ull, a1 = 0ull, b0 = 0ull, b1 = 0ull;
#pragma unroll
            for (int c2 = 0; c2 < 16; c2++) {
                ulonglong2 wq = wk2[c2], wv = wv2[c2];
                a0 = fma2_(wq.x, xp[2 * c2], a0); a1 = fma2_(wq.y, xp[2 * c2 + 1], a1);
                b0 = fma2_(wv.x, xp[2 * c2], b0); b1 = fma2_(wv.y, xp[2 * c2 + 1], b1);
            }
            kp[d] = add2_(a0, a1); vp[d] = add2_(b0, b1);
        }
        {
            float v0[4], v1[4];
#pragma unroll
            for (int e = 0; e < 4; e++) upk2(vp[e], v0[e], v1[e]);
            *(float4*)(vg0 + h * 4) = make_float4(v0[0], v0[1], v0[2], v0[3]);
            *(float4*)(vg0 + 32 + h * 4) = make_float4(v1[0], v1[1], v1[2], v1[3]);
        }
        u64 ss = mul2_(kp[0], kp[0]);
        ss = fma2_(kp[1], kp[1], ss); ss = fma2_(kp[2], kp[2], ss); ss = fma2_(kp[3], kp[3], ss);
        float s0, s1; upk2(ss, s0, s1);
        u64 knp = pk2(rsqrtf(s0), rsqrtf(s1));
        u64 kh[4];
#pragma unroll
        for (int d = 0; d < 4; d++) kh[d] = mul2_(kp[d], knp);
        float p[16];
#pragma unroll
        for (int d = 0; d < 4; d++)
#pragma unroll
            for (int e = 0; e < 4; e++) {
                float a, bb; upk2(mul2_(kh[d], vp[e]), a, bb);
                p[d * 4 + e] = a + bb;
            }
#pragma unroll
        for (int i = 0; i < 16; i++) {
            p[i] += __shfl_xor_sync(0xffffffffu, p[i], 16);
            p[i] += __shfl_xor_sync(0xffffffffu, p[i], 8);
            p[i] += __shfl_xor_sync(0xffffffffu, p[i], 4);
        }
        if (lane < 4) {
#pragma unroll
            for (int i = 0; i < 16; i++) accsh[warp][lane][h][i] = p[i];
        }
    }
    __syncthreads();
    {
        const int h = tid >> 4, de = tid & 15;
        float s = 0.f;
#pragma unroll
        for (int w = 0; w < 4; w++)
#pragma unroll
            for (int sb = 0; sb < 4; sb++) s += accsh[w][sb][h][de];
        g_part_la[(size_t)(b * NCH + ch) * 128 + tid] = s;
    }
}

// ---------------- K2: LA pass2 (R8-proven: c-outer streamed x, unchanged) ----------------
#define LA2_SMEM 55840
__global__ __launch_bounds__(128) void k_la_pass2(const float* __restrict__ rgb,
                                                  const float* __restrict__ qkvw,
                                                  const float* __restrict__ pw,
                                                  const float* __restrict__ pb,
                                                  const float* __restrict__ dw) {
    extern __shared__ __align__(16) char dynsm[];
    u64* qTdup = (u64*)dynsm;
    u64* projdup = qTdup + 1024;
    u64* attn_dup = projdup + 1024;
    float* vsh = (float*)(dynsm + 17408);
    float* dwsh = (float*)(dynsm + 55424);
    float* pbsh = (float*)(dynsm + 55712);
    const int b = blockIdx.y, ch = blockIdx.x, tid = threadIdx.x;
    const int warp = tid >> 5, lane = tid & 31;
    for (int i = tid; i < 1024; i += 128) {
        float a = qkvw[(i & 31) * 32 + (i >> 5)];
        qTdup[i] = pk2(a, a);
        float p_ = pw[i]; projdup[i] = pk2(p_, p_);
    }
    {
        float s = 0.f;
        for (int c2 = 0; c2 < NCH; c2++) s += g_part_la[(size_t)(b * NCH + c2) * 128 + tid];
        attn_dup[tid] = pk2(s, s);
    }
    if (tid < 72) dwsh[tid] = dw[tid];
    if (tid < 32) pbsh[tid] = pb[tid];
    const int l0b = ch * CHK;
    for (int i = tid; i < 264 * 8; i += 128) {
        int r = i >> 3, c4 = i & 7;
        int gl = l0b - 4 + r;
        float4 v = (gl >= 0 && gl < LN) ? *(const float4*)(g_vbuf + ((size_t)b * LN + gl) * 32 + c4 * 4)
                                        : make_float4(0.f, 0.f, 0.f, 0.f);
        *(float4*)(vsh + r * 36 + c4 * 4) = v;
    }
    __syncthreads();
    const int l0 = l0b + 2 * tid;
    const float* xr = rgb + (size_t)b * CN * LN;
    u64 q[32];
#pragma unroll
    for (int r = 0; r < 32; r++) q[r] = 0ull;
#pragma unroll 4
    for (int c = 0; c < 32; c++) {
        u64 xc = *(const u64*)(xr + (size_t)c * LN + l0);
        const ulonglong2* wt = (const ulonglong2*)&qTdup[c * 32];
#pragma unroll
        for (int j2 = 0; j2 < 16; j2++) {
            ulonglong2 w = wt[j2];
            q[2 * j2] = fma2_(w.x, xc, q[2 * j2]);
            q[2 * j2 + 1] = fma2_(w.y, xc, q[2 * j2 + 1]);
        }
    }
    const u64 HALFP = pk2(0.5f, 0.5f);
    u64 outp[32];
#pragma unroll
    for (int h = 0; h < HEADSN; h++) {
        u64* qh = &q[h * 4];
        u64 ss = mul2_(qh[0], qh[0]);
        ss = fma2_(qh[1], qh[1], ss); ss = fma2_(qh[2], qh[2], ss); ss = fma2_(qh[3], qh[3], ss);
        float s0, s1; upk2(ss, s0, s1);
        u64 qnp = pk2(rsqrtf(s0) * INV_PI, rsqrtf(s1) * INV_PI);
        float dc0[4] = {0.f, 0.f, 0.f, 0.f}, dc1[4] = {0.f, 0.f, 0.f, 0.f};
        u64 vcp[4];
        float4 aR = *(float4*)(vsh + (2 * tid) * 36 + h * 4);
#pragma unroll
        for (int t9 = 0; t9 < 9; t9++) {
            float4 nb = *(float4*)(vsh + (2 * tid + t9 + 1) * 36 + h * 4);
            float wd = dwsh[h * 9 + t9];
            dc0[0] += wd * aR.x; dc0[1] += wd * aR.y; dc0[2] += wd * aR.z; dc0[3] += wd * aR.w;
            dc1[0] += wd * nb.x; dc1[1] += wd * nb.y; dc1[2] += wd * nb.z; dc1[3] += wd * nb.w;
            if (t9 == 4) {
                vcp[0] = pk2(aR.x, nb.x); vcp[1] = pk2(aR.y, nb.y);
                vcp[2] = pk2(aR.z, nb.z); vcp[3] = pk2(aR.w, nb.w);
            }
            aR = nb;
        }
#pragma unroll
        for (int e = 0; e < 4; e++) {
            u64 t = mul2_(qh[0], attn_dup[h * 16 + e]);
            t = fma2_(qh[1], attn_dup[h * 16 + 4 + e], t);
            t = fma2_(qh[2], attn_dup[h * 16 + 8 + e], t);
            t = fma2_(qh[3], attn_dup[h * 16 + 12 + e], t);
            outp[h * 4 + e] = fma2_(qnp, t, mul2_(HALFP, vcp[e]));
        }
        u64 os = mul2_(outp[h * 4], outp[h * 4]);
        os = fma2_(outp[h * 4 + 1], outp[h * 4 + 1], os);
        os = fma2_(outp[h * 4 + 2], outp[h * 4 + 2], os);
        os = fma2_(outp[h * 4 + 3], outp[h * 4 + 3], os);
        float o0, o1; upk2(os, o0, o1);
        u64 onp = pk2(rsqrtf(o0), rsqrtf(o1));
#pragma unroll
        for (int e = 0; e < 4; e++)
            outp[h * 4 + e] = fma2_(outp[h * 4 + e], onp, pk2(dc0[e], dc1[e]));
    }
    __syncthreads();
    float* psum = vsh;
    float* pmax = vsh + 512;
#pragma unroll
    for (int c = 0; c < 32; c++) {
        const ulonglong2* w2 = (const ulonglong2*)&projdup[c * 32];
        u64 a0 = pk2(pbsh[c], pbsh[c]), a1 = 0ull;
#pragma unroll
        for (int j2 = 0; j2 < 16; j2++) {
            ulonglong2 w = w2[j2];
            a0 = fma2_(w.x, outp[2 * j2], a0); a1 = fma2_(w.y, outp[2 * j2 + 1], a1);
        }
        u64 a = add2_(a0, a1);
        *(u64*)(g_f1 + (size_t)b * CN * LN + (size_t)c * LN + l0) = a;
        float s0, s1; upk2(a, s0, s1);
        float sc = s0 + s1, mc = fmaxf(s0, s1);
        sc += __shfl_xor_sync(0xffffffffu, sc, 16); mc = fmaxf(mc, __shfl_xor_sync(0xffffffffu, mc, 16));
        sc += __shfl_xor_sync(0xffffffffu, sc, 8);  mc = fmaxf(mc, __shfl_xor_sync(0xffffffffu, mc, 8));
        sc += __shfl_xor_sync(0xffffffffu, sc, 4);  mc = fmaxf(mc, __shfl_xor_sync(0xffffffffu, mc, 4));
        if (lane < 4) { psum[(warp * 4 + lane) * 32 + c] = sc; pmax[(warp * 4 + lane) * 32 + c] = mc; }
    }
    __syncthreads();
    if (tid < 32) {
        float s = 0.f, m = -1e30f;
#pragma unroll
        for (int k = 0; k < 16; k++) { s += psum[k * 32 + tid]; m = fmaxf(m, pmax[k * 32 + tid]); }
        g_pf_sum[((size_t)b * NCH + ch) * 32 + tid] = s;
        g_pf_max[((size_t)b * NCH + ch) * 32 + tid] = m;
    }
}

// ---------------- K3: XCA pass1 (R8-proven, unchanged) ----------------
__global__ __launch_bounds__(128) void k_xca_pass1(const float* __restrict__ freq,
                                                   const float* __restrict__ qkvw) {
    __shared__ __align__(16) u64 wdup[64 * 32];
    __shared__ float accsh[4][4][HEADSN][24];
    const int b = blockIdx.y, ch = blockIdx.x, tid = threadIdx.x;
    const int warp = tid >> 5, lane = tid & 31;
    for (int i = tid; i < 64 * 32; i += 128) { float w = qkvw[i]; wdup[i] = pk2(w, w); }
    __syncthreads();
    const int l0 = ch * CHK + 2 * tid;
    const float* xr = freq + (size_t)b * CN * LN;
    u64 xp[32];
#pragma unroll
    for (int c = 0; c < 32; c++) xp[c] = *(const u64*)(xr + (size_t)c * LN + l0);
#pragma unroll
    for (int h = 0; h < HEADSN; h++) {
        u64 qp[4], kp[4];
#pragma unroll
        for (int d = 0; d < 4; d++) {
            const ulonglong2* wq2 = (const ulonglong2*)&wdup[(h * 4 + d) * 32];
            const ulonglong2* wk2 = (const ulonglong2*)&wdup[(32 + h * 4 + d) * 32];
            u64 a0 = 0ull, a1 = 0ull, b0 = 0ull, b1 = 0ull;
#pragma unroll
            for (int c2 = 0; c2 < 16; c2++) {
                ulonglong2 wq = wq2[c2], wk = wk2[c2];
                a0 = fma2_(wq.x, xp[2 * c2], a0); a1 = fma2_(wq.y, xp[2 * c2 + 1], a1);
                b0 = fma2_(wk.x, xp[2 * c2], b0); b1 = fma2_(wk.y, xp[2 * c2 + 1], b1);
            }
            qp[d] = add2_(a0, a1); kp[d] = add2_(b0, b1);
        }
        float p[24];
#pragma unroll
        for (int d = 0; d < 4; d++)
#pragma unroll
            for (int e = 0; e < 4; e++) {
                float a, bb; upk2(mul2_(qp[d], kp[e]), a, bb);
                p[d * 4 + e] = a + bb;
            }
#pragma unroll
        for (int d = 0; d < 4; d++) {
            float a, bb;
            upk2(mul2_(qp[d], qp[d]), a, bb); p[16 + d] = a + bb;
            upk2(mul2_(kp[d], kp[d]), a, bb); p[20 + d] = a + bb;
        }
#pragma unroll
        for (int i = 0; i < 24; i++) {
            p[i] += __shfl_xor_sync(0xffffffffu, p[i], 16);
            p[i] += __shfl_xor_sync(0xffffffffu, p[i], 8);
            p[i] += __shfl_xor_sync(0xffffffffu, p[i], 4);
        }
        if (lane < 4) {
#pragma unroll
            for (int i = 0; i < 24; i++) accsh[warp][lane][h][i] = p[i];
        }
    }
    __syncthreads();
    for (int i = tid; i < HEADSN * 24; i += 128) {
        const int h = i / 24, j = i % 24;
        float s = 0.f;
#pragma unroll
        for (int w = 0; w < 4; w++)
#pragma unroll
            for (int sb = 0; sb < 4; sb++) s += accsh[w][sb][h][j];
        g_part_x[((size_t)(b * NCH + ch) * HEADSN + h) * 24 + j] = s;
    }
}

// ---------------- K4: XCA pass2 — NEW row-pair packed GEMMs (no weight duplication) ----------------
// warp w owns rows 8w..8w+7 (heads 2w,2w+1); lane owns pixels {4*lane+0..3, 128+4*lane+0..3}.
// acc[rp][j] = {row 8w+2rp, row 8w+2rp+1} for pixel j.
#define XCA2_SMEM 41600
__global__ __launch_bounds__(128) void k_xca_pass2(const float* __restrict__ freq,
                                                   const float* __restrict__ qkvw,
                                                   const float* __restrict__ pw,
                                                   const float* __restrict__ pb,
                                                   const float* __restrict__ temp) {
    extern __shared__ __align__(16) char dynsm4[];
    u64* wpair = (u64*)dynsm4;                     // [c][r2]: {vw[2r2][c], vw[2r2+1][c]}   4096B
    u64* ppair = (u64*)(dynsm4 + 4096);            // [jj][r2]: {pw[2r2][jj], pw[2r2+1][jj]} 4096B
    float* attnsh = (float*)(dynsm4 + 8192);       // 128 floats -> 8704
    float* pbsh = (float*)(dynsm4 + 8704);         // 32 floats -> 8832
    float* xsh = (float*)(dynsm4 + 8832);          // 32x256 floats = 32768 -> 41600 (reused as y)
    const int b = blockIdx.y, ch = blockIdx.x, tid = threadIdx.x;
    const int w = tid >> 5, lane = tid & 31;
    const int l0b = ch * CHK;
    // stage weights as row-pairs (no duplication)
    for (int i = tid; i < 512; i += 128) {
        int c = i >> 4, r2 = i & 15;
        wpair[i] = pk2(qkvw[64 * 32 + (2 * r2) * 32 + c], qkvw[64 * 32 + (2 * r2 + 1) * 32 + c]);
        ppair[i] = pk2(pw[(2 * r2) * 32 + c], pw[(2 * r2 + 1) * 32 + c]);
    }
    if (tid < 32) pbsh[tid] = pb[tid];
    if (tid < 32) {   // folded attn softmax -> scalar attnsh
        const int h = tid >> 2, d = tid & 3;
        const float* base = g_part_x + (size_t)b * NCH * 192 + h * 24;
        float qk[4] = {0.f, 0.f, 0.f, 0.f}, qq = 0.f, kk[4] = {0.f, 0.f, 0.f, 0.f};
        for (int c2 = 0; c2 < NCH; c2++) {
            const float* pc = base + (size_t)c2 * 192;
            qk[0] += pc[d * 4 + 0]; qk[1] += pc[d * 4 + 1]; qk[2] += pc[d * 4 + 2]; qk[3] += pc[d * 4 + 3];
            qq += pc[16 + d];
            kk[0] += pc[20]; kk[1] += pc[21]; kk[2] += pc[22]; kk[3] += pc[23];
        }
        float nq = fmaxf(sqrtf(qq), 1e-12f);
        float t = temp[h];
        float a[4], m = -1e30f;
#pragma unroll
        for (int e = 0; e < 4; e++) {
            a[e] = qk[e] / (nq * fmaxf(sqrtf(kk[e]), 1e-12f)) * t;
            m = fmaxf(m, a[e]);
        }
        float sum = 0.f;
#pragma unroll
        for (int e = 0; e < 4; e++) { a[e] = expf(a[e] - m); sum += a[e]; }
        float inv = 1.f / sum;
#pragma unroll
        for (int e = 0; e < 4; e++) attnsh[h * 16 + d * 4 + e] = a[e] * inv;
    }
    // stage x tile
    {
        const float* xr = freq + (size_t)b * CN * LN + l0b;
        for (int i = tid; i < 2048; i += 128) {
            int c = i >> 6, p4 = i & 63;
            *(float4*)(xsh + c * 256 + p4 * 4) = *(const float4*)(xr + (size_t)c * LN + p4 * 4);
        }
    }
    __syncthreads();
    // GEMM1: v rows (row-pair packed)
    u64 acc[4][8];
#pragma unroll
    for (int rp = 0; rp < 4; rp++)
#pragma unroll
        for (int j = 0; j < 8; j++) acc[rp][j] = 0ull;
#pragma unroll 4
    for (int c = 0; c < 32; c++) {
        float4 xa = *(const float4*)(xsh + c * 256 + 4 * lane);
        float4 xb = *(const float4*)(xsh + c * 256 + 128 + 4 * lane);
        u64 xd[8];
        xd[0] = pk2(xa.x, xa.x); xd[1] = pk2(xa.y, xa.y); xd[2] = pk2(xa.z, xa.z); xd[3] = pk2(xa.w, xa.w);
        xd[4] = pk2(xb.x, xb.x); xd[5] = pk2(xb.y, xb.y); xd[6] = pk2(xb.z, xb.z); xd[7] = pk2(xb.w, xb.w);
        ulonglong2 wA = *(const ulonglong2*)&wpair[c * 16 + 4 * w];
        ulonglong2 wB = *(const ulonglong2*)&wpair[c * 16 + 4 * w + 2];
#pragma unroll
        for (int j = 0; j < 8; j++) {
            acc[0][j] = fma2_(wA.x, xd[j], acc[0][j]);
            acc[1][j] = fma2_(wA.y, xd[j], acc[1][j]);
            acc[2][j] = fma2_(wB.x, xd[j], acc[2][j]);
            acc[3][j] = fma2_(wB.y, xd[j], acc[3][j]);
        }
    }
    // attn apply: head hp uses acc[2hp] (ch 0,1) and acc[2hp+1] (ch 2,3)
#pragma unroll
    for (int hp = 0; hp < 2; hp++) {
        const float* ah = attnsh + (2 * w + hp) * 16;
        u64 A0[4], A1[4];
#pragma unroll
        for (int e = 0; e < 4; e++) {
            A0[e] = pk2(ah[e], ah[4 + e]);       // {a[d=0][e], a[d=1][e]}
            A1[e] = pk2(ah[8 + e], ah[12 + e]);  // {a[d=2][e], a[d=3][e]}
        }
#pragma unroll
        for (int j = 0; j < 8; j++) {
            float v0, v1, v2, v3;
            upk2(acc[2 * hp][j], v0, v1);
            upk2(acc[2 * hp + 1][j], v2, v3);
            u64 vd0 = pk2(v0, v0), vd1 = pk2(v1, v1), vd2 = pk2(v2, v2), vd3 = pk2(v3, v3);
            u64 o01 = mul2_(A0[0], vd0);
            o01 = fma2_(A0[1], vd1, o01); o01 = fma2_(A0[2], vd2, o01); o01 = fma2_(A0[3], vd3, o01);
            u64 o23 = mul2_(A1[0], vd0);
            o23 = fma2_(A1[1], vd1, o23); o23 = fma2_(A1[2], vd2, o23); o23 = fma2_(A1[3], vd3, o23);
            acc[2 * hp][j] = o01;
            acc[2 * hp + 1][j] = o23;
        }
    }
    __syncthreads();        // all xsh reads done -> transpose y into xsh
#pragma unroll
    for (int rp = 0; rp < 4; rp++) {
        float r0[8], r1[8];
#pragma unroll
        for (int j = 0; j < 8; j++) upk2(acc[rp][j], r0[j], r1[j]);
        int row0 = 8 * w + 2 * rp;
        *(float4*)(xsh + row0 * 256 + 4 * lane) = make_float4(r0[0], r0[1], r0[2], r0[3]);
        *(float4*)(xsh + row0 * 256 + 128 + 4 * lane) = make_float4(r0[4], r0[5], r0[6], r0[7]);
        *(float4*)(xsh + (row0 + 1) * 256 + 4 * lane) = make_float4(r1[0], r1[1], r1[2], r1[3]);
        *(float4*)(xsh + (row0 + 1) * 256 + 128 + 4 * lane) = make_float4(r1[4], r1[5], r1[6], r1[7]);
    }
    __syncthreads();
    // proj GEMM (same row-pair structure)
    u64 pa[4][8];
#pragma unroll
    for (int rp = 0; rp < 4; rp++) {
        u64 init = pk2(pbsh[8 * w + 2 * rp], pbsh[8 * w + 2 * rp + 1]);
#pragma unroll
        for (int j = 0; j < 8; j++) pa[rp][j] = init;
    }
#pragma unroll 4
    for (int jj = 0; jj < 32; jj++) {
        float4 ya = *(const float4*)(xsh + jj * 256 + 4 * lane);
        float4 yb = *(const float4*)(xsh + jj * 256 + 128 + 4 * lane);
        u64 yd[8];
        yd[0] = pk2(ya.x, ya.x); yd[1] = pk2(ya.y, ya.y); yd[2] = pk2(ya.z, ya.z); yd[3] = pk2(ya.w, ya.w);
        yd[4] = pk2(yb.x, yb.x); yd[5] = pk2(yb.y, yb.y); yd[6] = pk2(yb.z, yb.z); yd[7] = pk2(yb.w, yb.w);
        ulonglong2 wA = *(const ulonglong2*)&ppair[jj * 16 + 4 * w];
        ulonglong2 wB = *(const ulonglong2*)&ppair[jj * 16 + 4 * w + 2];
#pragma unroll
        for (int j = 0; j < 8; j++) {
            pa[0][j] = fma2_(wA.x, yd[j], pa[0][j]);
            pa[1][j] = fma2_(wA.y, yd[j], pa[1][j]);
            pa[2][j] = fma2_(wB.x, yd[j], pa[2][j]);
            pa[3][j] = fma2_(wB.y, yd[j], pa[3][j]);
        }
    }
    // store f2 + per-row pool (sum/max over the warp's 256 pixels)
    float* f2base = g_f2 + (size_t)b * CN * LN + l0b;
#pragma unroll
    for (int rp = 0; rp < 4; rp++) {
        float r0[8], r1[8];
#pragma unroll
        for (int j = 0; j < 8; j++) upk2(pa[rp][j], r0[j], r1[j]);
        int row0 = 8 * w + 2 * rp;
        *(float4*)(f2base + (size_t)row0 * LN + 4 * lane) = make_float4(r0[0], r0[1], r0[2], r0[3]);
        *(float4*)(f2base + (size_t)row0 * LN + 128 + 4 * lane) = make_float4(r0[4], r0[5], r0[6], r0[7]);
        *(float4*)(f2base + (size_t)(row0 + 1) * LN + 4 * lane) = make_float4(r1[0], r1[1], r1[2], r1[3]);
        *(float4*)(f2base + (size_t)(row0 + 1) * LN + 128 + 4 * lane) = make_float4(r1[4], r1[5], r1[6], r1[7]);
        float s0 = 0.f, m0 = -1e30f, s1 = 0.f, m1 = -1e30f;
#pragma unroll
        for (int j = 0; j < 8; j++) {
            s0 += r0[j]; m0 = fmaxf(m0, r0[j]);
            s1 += r1[j]; m1 = fmaxf(m1, r1[j]);
        }
#pragma unroll
        for (int off = 16; off > 0; off >>= 1) {
            s0 += __shfl_xor_sync(0xffffffffu, s0, off);
            m0 = fmaxf(m0, __shfl_xor_sync(0xffffffffu, m0, off));
            s1 += __shfl_xor_sync(0xffffffffu, s1, off);
            m1 = fmaxf(m1, __shfl_xor_sync(0xffffffffu, m1, off));
        }
        if (lane == 0) {
            size_t pbase = (size_t)(BN * NCH * 32) + ((size_t)b * NCH + ch) * 32;
            g_pf_sum[pbase + row0] = s0;     g_pf_max[pbase + row0] = m0;
            g_pf_sum[pbase + row0 + 1] = s1; g_pf_max[pbase + row0 + 1] = m1;
        }
    }
}

// ---------------- K5: channel MLPs + cross softmax (unchanged) ----------------
__global__ void k_cafm_vec(const float* __restrict__ a1w, const float* __restrict__ a1b,
                           const float* __restrict__ m1w, const float* __restrict__ m1b,
                           const float* __restrict__ a2w, const float* __restrict__ a2b,
                           const float* __restrict__ m2w, const float* __restrict__ m2b,
                           const float* __restrict__ a11w, const float* __restrict__ a11b,
                           const float* __restrict__ m11w, const float* __restrict__ m11b,
                           const float* __restrict__ a22w, const float* __restrict__ a22b,
                           const float* __restrict__ m22w, const float* __restrict__ m22b) {
    const int b = blockIdx.x, c = threadIdx.x;
    __shared__ float av1[32], mx1[32], av2[32], mx2[32];
    __shared__ float h1a[16], h1m[16], h2a[16], h2m[16];
    __shared__ float a1s[32], a2s[32];
    {
        float s1 = 0.f, m1 = -1e30f, s2 = 0.f, m2 = -1e30f;
        for (int chn = 0; chn < NCH; chn++) {
            s1 += g_pf_sum[((size_t)b * NCH + chn) * 32 + c];
            m1 = fmaxf(m1, g_pf_max[((size_t)b * NCH + chn) * 32 + c]);
            s2 += g_pf_sum[(size_t)(BN * NCH * 32) + ((size_t)b * NCH + chn) * 32 + c];
            m2 = fmaxf(m2, g_pf_max[(size_t)(BN * NCH * 32) + ((size_t)b * NCH + chn) * 32 + c]);
        }
        av1[c] = s1 * (1.f / LN); mx1[c] = m1;
        av2[c] = s2 * (1.f / LN); mx2[c] = m2;
    }
    __syncthreads();
    if (c < 16) {
        float s1 = a1b[c], s2 = m1b[c], s3 = a2b[c], s4 = m2b[c];
        for (int j = 0; j < 32; j++) {
            s1 += a1w[c * 32 + j] * av1[j];
            s2 += m1w[c * 32 + j] * mx1[j];
            s3 += a2w[c * 32 + j] * av2[j];
            s4 += m2w[c * 32 + j] * mx2[j];
        }
        h1a[c] = fmaxf(s1, 0.f); h1m[c] = fmaxf(s2, 0.f);
        h2a[c] = fmaxf(s3, 0.f); h2m[c] = fmaxf(s4, 0.f);
    }
    __syncthreads();
    {
        float s1 = a11b[c] + m11b[c];
        float s2 = a22b[c] + m22b[c];
        for (int j = 0; j < 16; j++) {
            s1 += a11w[c * 16 + j] * h1a[j] + m11w[c * 16 + j] * h1m[j];
            s2 += a22w[c * 16 + j] * h2a[j] + m22w[c * 16 + j] * h2m[j];
        }
        a1s[c] = s1; a2s[c] = s2;
    }
    __syncthreads();
    {
        float ac = a1s[c], m = -1e30f;
        for (int d = 0; d < 32; d++) m = fmaxf(m, ac * a2s[d]);
        float sum = 0.f;
        for (int d = 0; d < 32; d++) sum += expf(ac * a2s[d] - m);
        float inv = 1.f / sum;
        for (int d = 0; d < 32; d++) g_s1[(size_t)b * 1024 + c * 32 + d] = expf(ac * a2s[d] - m) * inv;
    }
    {
        float ac = a2s[c], m = -1e30f;
        for (int d = 0; d < 32; d++) m = fmaxf(m, ac * a1s[d]);
        float sum = 0.f;
        for (int d = 0; d < 32; d++) sum += expf(ac * a1s[d] - m);
        float inv = 1.f / sum;
        for (int d = 0; d < 32; d++) g_s2[(size_t)b * 1024 + c * 32 + d] = expf(ac * a1s[d] - m) * inv;
    }
}

// ---------------- K6: fused s@f + mean/max over C (R8-proven d-outer streaming) ----------------
__global__ __launch_bounds__(128) void k_gate_pool() {
    __shared__ __align__(16) u64 s1Td[1024];
    __shared__ __align__(16) u64 s2Td[1024];
    const int b = blockIdx.y, ch = blockIdx.x, tid = threadIdx.x;
    for (int i = tid; i < 1024; i += 128) {
        float a = g_s1[(size_t)b * 1024 + (i & 31) * 32 + (i >> 5)];
        s1Td[i] = pk2(a, a);
        float c2 = g_s2[(size_t)b * 1024 + (i & 31) * 32 + (i >> 5)];
        s2Td[i] = pk2(c2, c2);
    }
    __syncthreads();
    const int l0 = ch * CHK + 2 * tid;
    {
        u64 acc[32];
#pragma unroll
        for (int c = 0; c < 32; c++) acc[c] = 0ull;
#pragma unroll 4
        for (int d = 0; d < 32; d++) {
            u64 fd = *(const u64*)(g_f1 + (size_t)b * CN * LN + (size_t)d * LN + l0);
            const ulonglong2* sp = (const ulonglong2*)&s1Td[d * 32];
#pragma unroll
            for (int c2 = 0; c2 < 16; c2++) {
                ulonglong2 w = sp[c2];
                acc[2 * c2] = fma2_(w.x, fd, acc[2 * c2]);
                acc[2 * c2 + 1] = fma2_(w.y, fd, acc[2 * c2 + 1]);
            }
        }
        u64 sump = 0ull;
        float mx0 = -1e30f, mx1 = -1e30f;
#pragma unroll
        for (int c = 0; c < 32; c++) {
            sump = add2_(sump, acc[c]);
            float v0, v1; upk2(acc[c], v0, v1);
            mx0 = fmaxf(mx0, v0); mx1 = fmaxf(mx1, v1);
        }
        *(u64*)(g_pooled1 + (size_t)b * 2 * LN + l0) = mul2_(sump, pk2(1.f / 32.f, 1.f / 32.f));
        *(u64*)(g_pooled1 + (size_t)b * 2 * LN + LN + l0) = pk2(mx0, mx1);
    }
    {
        u64 acc[32];
#pragma unroll
        for (int c = 0; c < 32; c++) acc[c] = 0ull;
#pragma unroll 4
        for (int d = 0; d < 32; d++) {
            u64 fd = *(const u64*)(g_f2 + (size_t)b * CN * LN + (size_t)d * LN + l0);
            const ulonglong2* sp = (const ulonglong2*)&s2Td[d * 32];
#pragma unroll
            for (int c2 = 0; c2 < 16; c2++) {
                ulonglong2 w = sp[c2];
                acc[2 * c2] = fma2_(w.x, fd, acc[2 * c2]);
                acc[2 * c2 + 1] = fma2_(w.y, fd, acc[2 * c2 + 1]);
            }
        }
        u64 sump = 0ull;
        float mx0 = -1e30f, mx1 = -1e30f;
#pragma unroll
        for (int c = 0; c < 32; c++) {
            sump = add2_(sump, acc[c]);
            float v0, v1; upk2(acc[c], v0, v1);
            mx0 = fmaxf(mx0, v0); mx1 = fmaxf(mx1, v1);
        }
        *(u64*)(g_pooled2 + (size_t)b * 2 * LN + l0) = mul2_(sump, pk2(1.f / 32.f, 1.f / 32.f));
        *(u64*)(g_pooled2 + (size_t)b * 2 * LN + LN + l0) = pk2(mx0, mx1);
    }
}

// ---------------- K7: fused conv1 + conv2 + softmax stats (unchanged) ----------------
__global__ __launch_bounds__(256) void k_gate_conv(const float* __restrict__ c1w, const float* __restrict__ c1b,
                                                   const float* __restrict__ c2w, const float* __restrict__ c2b) {
    const int b = blockIdx.x, gate = blockIdx.y, tid = threadIdx.x;
    __shared__ float y1s[LN];
    __shared__ float red[256];
    const float* pin = (gate ? g_pooled2 : g_pooled1) + (size_t)b * 2 * LN;
    float* yo = (gate ? g_y2b : g_y2a) + (size_t)b * LN;
    float w1[18];
#pragma unroll
    for (int i = 0; i < 18; i++) w1[i] = c1w[i];
    float b1 = c1b[0];
    float w2[9];
#pragma unroll
    for (int i = 0; i < 9; i++) w2[i] = c2w[i];
    float b2 = c2b[0];
    for (int p = tid; p < LN; p += 256) {
        int hh = p / WN, ww = p % WN;
        float acc = b1;
#pragma unroll
        for (int ci = 0; ci < 2; ci++)
#pragma unroll
            for (int kh = 0; kh < 3; kh++) {
                int ih = hh + kh - 1;
                if (ih < 0 || ih >= HN) continue;
#pragma unroll
                for (int kw = 0; kw < 3; kw++) {
                    int iw = ww + kw - 1;
                    if (iw < 0 || iw >= WN) continue;
                    acc += pin[(size_t)ci * LN + ih * WN + iw] * w1[(ci * 3 + kh) * 3 + kw];
                }
            }
        y1s[p] = fmaxf(acc, 0.f);
    }
    __syncthreads();
    float yl[25];
    float mloc = -1e30f;
    int idx = 0;
    for (int p = tid; p < LN; p += 256, idx++) {
        int hh = p / WN, ww = p % WN;
        float acc = b2;
#pragma unroll
        for (int kh = 0; kh < 3; kh++) {
            int ih = hh + kh - 1;
            if (ih < 0 || ih >= HN) continue;
#pragma unroll
            for (int kw = 0; kw < 3; kw++) {
                int iw = ww + kw - 1;
                if (iw < 0 || iw >= WN) continue;
                acc += y1s[ih * WN + iw] * w2[kh * 3 + kw];
            }
        }
        yo[p] = acc;
        yl[idx] = acc;
        mloc = fmaxf(mloc, acc);
    }
    red[tid] = mloc;
    __syncthreads();
    for (int o = 128; o > 0; o >>= 1) { if (tid < o) red[tid] = fmaxf(red[tid], red[tid + o]); __syncthreads(); }
    float gm = red[0];
    __syncthreads();
    float sloc = 0.f;
#pragma unroll
    for (int i = 0; i < 25; i++) sloc += expf(yl[i] - gm);
    red[tid] = sloc;
    __syncthreads();
    for (int o = 128; o > 0; o >>= 1) { if (tid < o) red[tid] += red[tid + o]; __syncthreads(); }
    if (tid == 0) { g_gstat[(b * 2 + gate) * 2] = gm; g_gstat[(b * 2 + gate) * 2 + 1] = red[0]; }
}

// ---------------- K8: final gated residual combine (unchanged) ----------------
__global__ __launch_bounds__(256) void k_final(float* __restrict__ out) {
    const int NT4 = BN * CN * LN / 4;
    int i4 = blockIdx.x * 256 + threadIdx.x;
    if (i4 >= NT4) return;
    size_t i = (size_t)i4 * 4;
    int b = (int)(i / (CN * LN));
    int rem = (int)(i - (size_t)b * CN * LN);
    int l = rem % LN;
    float4 f1v = *(const float4*)(g_f1 + i);
    float4 f2v = *(const float4*)(g_f2 + i);
    float4 y1v = *(const float4*)(g_y2a + (size_t)b * LN + l);
    float4 y2v = *(const float4*)(g_y2b + (size_t)b * LN + l);
    float m1 = g_gstat[b * 4 + 0], s1i = 1.f / g_gstat[b * 4 + 1];
    float m2 = g_gstat[b * 4 + 2], s2i = 1.f / g_gstat[b * 4 + 3];
    float4 o;
    o.x = f1v.x * (1.f + expf(y1v.x - m1) * s1i) + f2v.x * (1.f + expf(y2v.x - m2) * s2i);
    o.y = f1v.y * (1.f + expf(y1v.y - m1) * s1i) + f2v.y * (1.f + expf(y2v.y - m2) * s2i);
    o.z = f1v.z * (1.f + expf(y1v.z - m1) * s1i) + f2v.z * (1.f + expf(y2v.z - m2) * s2i);
    o.w = f1v.w * (1.f + expf(y1v.w - m1) * s1i) + f2v.w * (1.f + expf(y2v.w - m2) * s2i);
    *(float4*)(out + i) = o;
}

// ---------------- launch ----------------
extern "C" void kernel_launch(void* const* d_in, const int* in_sizes, int n_in,
                              void* d_out, int out_size) {
    const float* rgb     = (const float*)d_in[0];
    const float* freq    = (const float*)d_in[1];
    const float* la_qkv  = (const float*)d_in[2];
    const float* la_pw   = (const float*)d_in[3];
    const float* la_pb   = (const float*)d_in[4];
    const float* la_dw   = (const float*)d_in[5];
    const float* xa_qkv  = (const float*)d_in[6];
    const float* xa_temp = (const float*)d_in[7];
    const float* xa_pw   = (const float*)d_in[8];
    const float* xa_pb   = (const float*)d_in[9];
    const float* c1w     = (const float*)d_in[10];
    const float* c1b     = (const float*)d_in[11];
    const float* c2w     = (const float*)d_in[12];
    const float* c2b     = (const float*)d_in[13];
    const float* avg1_w  = (const float*)d_in[14];
    const float* avg1_b  = (const float*)d_in[15];
    const float* max1_w  = (const float*)d_in[16];
    const float* max1_b  = (const float*)d_in[17];
    const float* avg2_w  = (const float*)d_in[18];
    const float* avg2_b  = (const float*)d_in[19];
    const float* max2_w  = (const float*)d_in[20];
    const float* max2_b  = (const float*)d_in[21];
    const float* avg11_w = (const float*)d_in[22];
    const float* avg11_b = (const float*)d_in[23];
    const float* max11_w = (const float*)d_in[24];
    const float* max11_b = (const float*)d_in[25];
    const float* avg22_w = (const float*)d_in[26];
    const float* avg22_b = (const float*)d_in[27];
    const float* max22_w = (const float*)d_in[28];
    const float* max22_b = (const float*)d_in[29];
    float* out = (float*)d_out;

    static int smem_set = 0;
    if (!smem_set) {
        cudaFuncSetAttribute(k_la_pass2, cudaFuncAttributeMaxDynamicSharedMemorySize, LA2_SMEM);
        cudaFuncSetAttribute(k_xca_pass2, cudaFuncAttributeMaxDynamicSharedMemorySize, XCA2_SMEM);
        smem_set = 1;
    }

    dim3 gBL(NCH, BN);
    k_la_pass1<<<gBL, 128>>>(rgb, la_qkv);
    k_xca_pass1<<<gBL, 128>>>(freq, xa_qkv);
    k_la_pass2<<<gBL, 128, LA2_SMEM>>>(rgb, la_qkv, la_pw, la_pb, la_dw);
    k_xca_pass2<<<gBL, 128, XCA2_SMEM>>>(freq, xa_qkv, xa_pw, xa_pb, xa_temp);
    k_cafm_vec<<<BN, 32>>>(avg1_w, avg1_b, max1_w, max1_b,
                           avg2_w, avg2_b, max2_w, max2_b,
                           avg11_w, avg11_b, max11_w, max11_b,
                           avg22_w, avg22_b, max22_w, max22_b);
    k_gate_pool<<<gBL, 128>>>();
    k_gate_conv<<<dim3(BN, 2), 256>>>(c1w, c1b, c2w, c2b);
    k_final<<<(BN * CN * LN / 4 + 255) / 256, 256>>>(out);
}

// round 14
// speedup vs baseline: 1.4708x; 1.4708x over previous
#include <cuda_runtime.h>

#define BN 64
#define CN 32
#define HN 80
#define WN 80
#define LN 6400
#define HEADSN 8
#define NCH 25
#define CHK 256
#define INV_PI 0.31830988618379067f

typedef unsigned long long u64;

__device__ __forceinline__ u64 pk2(float lo, float hi) {
    u64 r; asm("mov.b64 %0,{%1,%2};" : "=l"(r) : "f"(lo), "f"(hi)); return r;
}
__device__ __forceinline__ void upk2(u64 a, float& lo, float& hi) {
    asm("mov.b64 {%0,%1},%2;" : "=f"(lo), "=f"(hi) : "l"(a));
}
__device__ __forceinline__ u64 fma2_(u64 a, u64 b, u64 c) {
    u64 d; asm("fma.rn.f32x2 %0,%1,%2,%3;" : "=l"(d) : "l"(a), "l"(b), "l"(c)); return d;
}
__device__ __forceinline__ u64 add2_(u64 a, u64 b) {
    u64 d; asm("add.rn.f32x2 %0,%1,%2;" : "=l"(d) : "l"(a), "l"(b)); return d;
}
__device__ __forceinline__ u64 mul2_(u64 a, u64 b) {
    u64 d; asm("mul.rn.f32x2 %0,%1,%2;" : "=l"(d) : "l"(a), "l"(b)); return d;
}

// ---------------- device scratch ----------------
static __device__ float g_vbuf[(size_t)BN * LN * CN];
static __device__ float g_f1[(size_t)BN * CN * LN];
static __device__ float g_f2[(size_t)BN * CN * LN];
static __device__ float g_part_la[BN * NCH * HEADSN * 16];
static __device__ float g_part_x[BN * NCH * HEADSN * 24];
static __device__ float g_pf_sum[2 * BN * NCH * 32];
static __device__ float g_pf_max[2 * BN * NCH * 32];
static __device__ float g_s1[BN * CN * CN];
static __device__ float g_s2[BN * CN * CN];
static __device__ float g_pooled1[BN * 2 * LN];
static __device__ float g_pooled2[BN * 2 * LN];
static __device__ float g_y2a[BN * LN];
static __device__ float g_y2b[BN * LN];
static __device__ float g_gstat[BN * 2 * 2];

// ---------------- K1: LA pass1 (R8-proven, unchanged) ----------------
__global__ __launch_bounds__(128) void k_la_pass1(const float* __restrict__ rgb,
                                                  const float* __restrict__ qkvw) {
    __shared__ __align__(16) u64 wdup[64 * 32];
    __shared__ float accsh[4][4][HEADSN][16];
    const int b = blockIdx.y, ch = blockIdx.x, tid = threadIdx.x;
    const int warp = tid >> 5, lane = tid & 31;
    for (int i = tid; i < 64 * 32; i += 128) { float w = qkvw[32 * 32 + i]; wdup[i] = pk2(w, w); }
    __syncthreads();
    const int l0 = ch * CHK + 2 * tid;
    const float* xr = rgb + (size_t)b * CN * LN;
    u64 xp[32];
#pragma unroll
    for (int c = 0; c < 32; c++) xp[c] = *(const u64*)(xr + (size_t)c * LN + l0);
    float* vg0 = g_vbuf + ((size_t)b * LN + l0) * 32;
#pragma unroll
    for (int h = 0; h < HEADSN; h++) {
        u64 kp[4], vp[4];
#pragma unroll
        for (int d = 0; d < 4; d++) {
            const ulonglong2* wk2 = (const ulonglong2*)&wdup[(h * 4 + d) * 32];
            const ulonglong2* wv2 = (const ulonglong2*)&wdup[(32 + h * 4 + d) * 32];
            u64 a0 = 0ull, a1 = 0ull, b0 = 0ull, b1 = 0ull;
#pragma unroll
            for (int c2 = 0; c2 < 16; c2++) {
                ulonglong2 wq = wk2[c2], wv = wv2[c2];
                a0 = fma2_(wq.x, xp[2 * c2], a0); a1 = fma2_(wq.y, xp[2 * c2 + 1], a1);
                b0 = fma2_(wv.x, xp[2 * c2], b0); b1 = fma2_(wv.y, xp[2 * c2 + 1], b1);
            }
            kp[d] = add2_(a0, a1); vp[d] = add2_(b0, b1);
        }
        {
            float v0[4], v1[4];
#pragma unroll
            for (int e = 0; e < 4; e++) upk2(vp[e], v0[e], v1[e]);
            *(float4*)(vg0 + h * 4) = make_float4(v0[0], v0[1], v0[2], v0[3]);
            *(float4*)(vg0 + 32 + h * 4) = make_float4(v1[0], v1[1], v1[2], v1[3]);
        }
        u64 ss = mul2_(kp[0], kp[0]);
        ss = fma2_(kp[1], kp[1], ss); ss = fma2_(kp[2], kp[2], ss); ss = fma2_(kp[3], kp[3], ss);
        float s0, s1; upk2(ss, s0, s1);
        u64 knp = pk2(rsqrtf(s0), rsqrtf(s1));
        u64 kh[4];
#pragma unroll
        for (int d = 0; d < 4; d++) kh[d] = mul2_(kp[d], knp);
        float p[16];
#pragma unroll
        for (int d = 0; d < 4; d++)
#pragma unroll
            for (int e = 0; e < 4; e++) {
                float a, bb; upk2(mul2_(kh[d], vp[e]), a, bb);
                p[d * 4 + e] = a + bb;
            }
#pragma unroll
        for (int i = 0; i < 16; i++) {
            p[i] += __shfl_xor_sync(0xffffffffu, p[i], 16);
            p[i] += __shfl_xor_sync(0xffffffffu, p[i], 8);
            p[i] += __shfl_xor_sync(0xffffffffu, p[i], 4);
        }
        if (lane < 4) {
#pragma unroll
            for (int i = 0; i < 16; i++) accsh[warp][lane][h][i] = p[i];
        }
    }
    __syncthreads();
    {
        const int h = tid >> 4, de = tid & 15;
        float s = 0.f;
#pragma unroll
        for (int w = 0; w < 4; w++)
#pragma unroll
            for (int sb = 0; sb < 4; sb++) s += accsh[w][sb][h][de];
        g_part_la[(size_t)(b * NCH + ch) * 128 + tid] = s;
    }
}

// ---------------- K2: LA pass2 (R8-proven: c-outer streamed x, unchanged) ----------------
#define LA2_SMEM 55840
__global__ __launch_bounds__(128) void k_la_pass2(const float* __restrict__ rgb,
                                                  const float* __restrict__ qkvw,
                                                  const float* __restrict__ pw,
                                                  const float* __restrict__ pb,
                                                  const float* __restrict__ dw) {
    extern __shared__ __align__(16) char dynsm[];
    u64* qTdup = (u64*)dynsm;
    u64* projdup = qTdup + 1024;
    u64* attn_dup = projdup + 1024;
    float* vsh = (float*)(dynsm + 17408);
    float* dwsh = (float*)(dynsm + 55424);
    float* pbsh = (float*)(dynsm + 55712);
    const int b = blockIdx.y, ch = blockIdx.x, tid = threadIdx.x;
    const int warp = tid >> 5, lane = tid & 31;
    for (int i = tid; i < 1024; i += 128) {
        float a = qkvw[(i & 31) * 32 + (i >> 5)];
        qTdup[i] = pk2(a, a);
        float p_ = pw[i]; projdup[i] = pk2(p_, p_);
    }
    {
        float s = 0.f;
        for (int c2 = 0; c2 < NCH; c2++) s += g_part_la[(size_t)(b * NCH + c2) * 128 + tid];
        attn_dup[tid] = pk2(s, s);
    }
    if (tid < 72) dwsh[tid] = dw[tid];
    if (tid < 32) pbsh[tid] = pb[tid];
    const int l0b = ch * CHK;
    for (int i = tid; i < 264 * 8; i += 128) {
        int r = i >> 3, c4 = i & 7;
        int gl = l0b - 4 + r;
        float4 v = (gl >= 0 && gl < LN) ? *(const float4*)(g_vbuf + ((size_t)b * LN + gl) * 32 + c4 * 4)
                                        : make_float4(0.f, 0.f, 0.f, 0.f);
        *(float4*)(vsh + r * 36 + c4 * 4) = v;
    }
    __syncthreads();
    const int l0 = l0b + 2 * tid;
    const float* xr = rgb + (size_t)b * CN * LN;
    u64 q[32];
#pragma unroll
    for (int r = 0; r < 32; r++) q[r] = 0ull;
#pragma unroll 4
    for (int c = 0; c < 32; c++) {
        u64 xc = *(const u64*)(xr + (size_t)c * LN + l0);
        const ulonglong2* wt = (const ulonglong2*)&qTdup[c * 32];
#pragma unroll
        for (int j2 = 0; j2 < 16; j2++) {
            ulonglong2 w = wt[j2];
            q[2 * j2] = fma2_(w.x, xc, q[2 * j2]);
            q[2 * j2 + 1] = fma2_(w.y, xc, q[2 * j2 + 1]);
        }
    }
    const u64 HALFP = pk2(0.5f, 0.5f);
    u64 outp[32];
#pragma unroll
    for (int h = 0; h < HEADSN; h++) {
        u64* qh = &q[h * 4];
        u64 ss = mul2_(qh[0], qh[0]);
        ss = fma2_(qh[1], qh[1], ss); ss = fma2_(qh[2], qh[2], ss); ss = fma2_(qh[3], qh[3], ss);
        float s0, s1; upk2(ss, s0, s1);
        u64 qnp = pk2(rsqrtf(s0) * INV_PI, rsqrtf(s1) * INV_PI);
        float dc0[4] = {0.f, 0.f, 0.f, 0.f}, dc1[4] = {0.f, 0.f, 0.f, 0.f};
        u64 vcp[4];
        float4 aR = *(float4*)(vsh + (2 * tid) * 36 + h * 4);
#pragma unroll
        for (int t9 = 0; t9 < 9; t9++) {
            float4 nb = *(float4*)(vsh + (2 * tid + t9 + 1) * 36 + h * 4);
            float wd = dwsh[h * 9 + t9];
            dc0[0] += wd * aR.x; dc0[1] += wd * aR.y; dc0[2] += wd * aR.z; dc0[3] += wd * aR.w;
            dc1[0] += wd * nb.x; dc1[1] += wd * nb.y; dc1[2] += wd * nb.z; dc1[3] += wd * nb.w;
            if (t9 == 4) {
                vcp[0] = pk2(aR.x, nb.x); vcp[1] = pk2(aR.y, nb.y);
                vcp[2] = pk2(aR.z, nb.z); vcp[3] = pk2(aR.w, nb.w);
            }
            aR = nb;
        }
#pragma unroll
        for (int e = 0; e < 4; e++) {
            u64 t = mul2_(qh[0], attn_dup[h * 16 + e]);
            t = fma2_(qh[1], attn_dup[h * 16 + 4 + e], t);
            t = fma2_(qh[2], attn_dup[h * 16 + 8 + e], t);
            t = fma2_(qh[3], attn_dup[h * 16 + 12 + e], t);
            outp[h * 4 + e] = fma2_(qnp, t, mul2_(HALFP, vcp[e]));
        }
        u64 os = mul2_(outp[h * 4], outp[h * 4]);
        os = fma2_(outp[h * 4 + 1], outp[h * 4 + 1], os);
        os = fma2_(outp[h * 4 + 2], outp[h * 4 + 2], os);
        os = fma2_(outp[h * 4 + 3], outp[h * 4 + 3], os);
        float o0, o1; upk2(os, o0, o1);
        u64 onp = pk2(rsqrtf(o0), rsqrtf(o1));
#pragma unroll
        for (int e = 0; e < 4; e++)
            outp[h * 4 + e] = fma2_(outp[h * 4 + e], onp, pk2(dc0[e], dc1[e]));
    }
    __syncthreads();
    float* psum = vsh;
    float* pmax = vsh + 512;
#pragma unroll
    for (int c = 0; c < 32; c++) {
        const ulonglong2* w2 = (const ulonglong2*)&projdup[c * 32];
        u64 a0 = pk2(pbsh[c], pbsh[c]), a1 = 0ull;
#pragma unroll
        for (int j2 = 0; j2 < 16; j2++) {
            ulonglong2 w = w2[j2];
            a0 = fma2_(w.x, outp[2 * j2], a0); a1 = fma2_(w.y, outp[2 * j2 + 1], a1);
        }
        u64 a = add2_(a0, a1);
        *(u64*)(g_f1 + (size_t)b * CN * LN + (size_t)c * LN + l0) = a;
        float s0, s1; upk2(a, s0, s1);
        float sc = s0 + s1, mc = fmaxf(s0, s1);
        sc += __shfl_xor_sync(0xffffffffu, sc, 16); mc = fmaxf(mc, __shfl_xor_sync(0xffffffffu, mc, 16));
        sc += __shfl_xor_sync(0xffffffffu, sc, 8);  mc = fmaxf(mc, __shfl_xor_sync(0xffffffffu, mc, 8));
        sc += __shfl_xor_sync(0xffffffffu, sc, 4);  mc = fmaxf(mc, __shfl_xor_sync(0xffffffffu, mc, 4));
        if (lane < 4) { psum[(warp * 4 + lane) * 32 + c] = sc; pmax[(warp * 4 + lane) * 32 + c] = mc; }
    }
    __syncthreads();
    if (tid < 32) {
        float s = 0.f, m = -1e30f;
#pragma unroll
        for (int k = 0; k < 16; k++) { s += psum[k * 32 + tid]; m = fmaxf(m, pmax[k * 32 + tid]); }
        g_pf_sum[((size_t)b * NCH + ch) * 32 + tid] = s;
        g_pf_max[((size_t)b * NCH + ch) * 32 + tid] = m;
    }
}

// ---------------- K3: XCA pass1 (R8-proven, unchanged) ----------------
__global__ __launch_bounds__(128) void k_xca_pass1(const float* __restrict__ freq,
                                                   const float* __restrict__ qkvw) {
    __shared__ __align__(16) u64 wdup[64 * 32];
    __shared__ float accsh[4][4][HEADSN][24];
    const int b = blockIdx.y, ch = blockIdx.x, tid = threadIdx.x;
    const int warp = tid >> 5, lane = tid & 31;
    for (int i = tid; i < 64 * 32; i += 128) { float w = qkvw[i]; wdup[i] = pk2(w, w); }
    __syncthreads();
    const int l0 = ch * CHK + 2 * tid;
    const float* xr = freq + (size_t)b * CN * LN;
    u64 xp[32];
#pragma unroll
    for (int c = 0; c < 32; c++) xp[c] = *(const u64*)(xr + (size_t)c * LN + l0);
#pragma unroll
    for (int h = 0; h < HEADSN; h++) {
        u64 qp[4], kp[4];
#pragma unroll
        for (int d = 0; d < 4; d++) {
            const ulonglong2* wq2 = (const ulonglong2*)&wdup[(h * 4 + d) * 32];
            const ulonglong2* wk2 = (const ulonglong2*)&wdup[(32 + h * 4 + d) * 32];
            u64 a0 = 0ull, a1 = 0ull, b0 = 0ull, b1 = 0ull;
#pragma unroll
            for (int c2 = 0; c2 < 16; c2++) {
                ulonglong2 wq = wq2[c2], wk = wk2[c2];
                a0 = fma2_(wq.x, xp[2 * c2], a0); a1 = fma2_(wq.y, xp[2 * c2 + 1], a1);
                b0 = fma2_(wk.x, xp[2 * c2], b0); b1 = fma2_(wk.y, xp[2 * c2 + 1], b1);
            }
            qp[d] = add2_(a0, a1); kp[d] = add2_(b0, b1);
        }
        float p[24];
#pragma unroll
        for (int d = 0; d < 4; d++)
#pragma unroll
            for (int e = 0; e < 4; e++) {
                float a, bb; upk2(mul2_(qp[d], kp[e]), a, bb);
                p[d * 4 + e] = a + bb;
            }
#pragma unroll
        for (int d = 0; d < 4; d++) {
            float a, bb;
            upk2(mul2_(qp[d], qp[d]), a, bb); p[16 + d] = a + bb;
            upk2(mul2_(kp[d], kp[d]), a, bb); p[20 + d] = a + bb;
        }
#pragma unroll
        for (int i = 0; i < 24; i++) {
            p[i] += __shfl_xor_sync(0xffffffffu, p[i], 16);
            p[i] += __shfl_xor_sync(0xffffffffu, p[i], 8);
            p[i] += __shfl_xor_sync(0xffffffffu, p[i], 4);
        }
        if (lane < 4) {
#pragma unroll
            for (int i = 0; i < 24; i++) accsh[warp][lane][h][i] = p[i];
        }
    }
    __syncthreads();
    for (int i = tid; i < HEADSN * 24; i += 128) {
        const int h = i / 24, j = i % 24;
        float s = 0.f;
#pragma unroll
        for (int w = 0; w < 4; w++)
#pragma unroll
            for (int sb = 0; sb < 4; sb++) s += accsh[w][sb][h][j];
        g_part_x[((size_t)(b * NCH + ch) * HEADSN + h) * 24 + j] = s;
    }
}

// ---------------- K4: XCA pass2 — row-pair packed GEMMs (R13, kernel-level best) ----------------
#define XCA2_SMEM 41600
__global__ __launch_bounds__(128) void k_xca_pass2(const float* __restrict__ freq,
                                                   const float* __restrict__ qkvw,
                                                   const float* __restrict__ pw,
                                                   const float* __restrict__ pb,
                                                   const float* __restrict__ temp) {
    extern __shared__ __align__(16) char dynsm4[];
    u64* wpair = (u64*)dynsm4;                     // [c][r2]: {vw[2r2][c], vw[2r2+1][c]}
    u64* ppair = (u64*)(dynsm4 + 4096);            // [jj][r2]: {pw[2r2][jj], pw[2r2+1][jj]}
    float* attnsh = (float*)(dynsm4 + 8192);
    float* pbsh = (float*)(dynsm4 + 8704);
    float* xsh = (float*)(dynsm4 + 8832);          // 32x256 floats (reused as y)
    const int b = blockIdx.y, ch = blockIdx.x, tid = threadIdx.x;
    const int w = tid >> 5, lane = tid & 31;
    const int l0b = ch * CHK;
    for (int i = tid; i < 512; i += 128) {
        int c = i >> 4, r2 = i & 15;
        wpair[i] = pk2(qkvw[64 * 32 + (2 * r2) * 32 + c], qkvw[64 * 32 + (2 * r2 + 1) * 32 + c]);
        ppair[i] = pk2(pw[(2 * r2) * 32 + c], pw[(2 * r2 + 1) * 32 + c]);
    }
    if (tid < 32) pbsh[tid] = pb[tid];
    if (tid < 32) {
        const int h = tid >> 2, d = tid & 3;
        const float* base = g_part_x + (size_t)b * NCH * 192 + h * 24;
        float qk[4] = {0.f, 0.f, 0.f, 0.f}, qq = 0.f, kk[4] = {0.f, 0.f, 0.f, 0.f};
        for (int c2 = 0; c2 < NCH; c2++) {
            const float* pc = base + (size_t)c2 * 192;
            qk[0] += pc[d * 4 + 0]; qk[1] += pc[d * 4 + 1]; qk[2] += pc[d * 4 + 2]; qk[3] += pc[d * 4 + 3];
            qq += pc[16 + d];
            kk[0] += pc[20]; kk[1] += pc[21]; kk[2] += pc[22]; kk[3] += pc[23];
        }
        float nq = fmaxf(sqrtf(qq), 1e-12f);
        float t = temp[h];
        float a[4], m = -1e30f;
#pragma unroll
        for (int e = 0; e < 4; e++) {
            a[e] = qk[e] / (nq * fmaxf(sqrtf(kk[e]), 1e-12f)) * t;
            m = fmaxf(m, a[e]);
        }
        float sum = 0.f;
#pragma unroll
        for (int e = 0; e < 4; e++) { a[e] = expf(a[e] - m); sum += a[e]; }
        float inv = 1.f / sum;
#pragma unroll
        for (int e = 0; e < 4; e++) attnsh[h * 16 + d * 4 + e] = a[e] * inv;
    }
    {
        const float* xr = freq + (size_t)b * CN * LN + l0b;
        for (int i = tid; i < 2048; i += 128) {
            int c = i >> 6, p4 = i & 63;
            *(float4*)(xsh + c * 256 + p4 * 4) = *(const float4*)(xr + (size_t)c * LN + p4 * 4);
        }
    }
    __syncthreads();
    u64 acc[4][8];
#pragma unroll
    for (int rp = 0; rp < 4; rp++)
#pragma unroll
        for (int j = 0; j < 8; j++) acc[rp][j] = 0ull;
#pragma unroll 4
    for (int c = 0; c < 32; c++) {
        float4 xa = *(const float4*)(xsh + c * 256 + 4 * lane);
        float4 xb = *(const float4*)(xsh + c * 256 + 128 + 4 * lane);
        u64 xd[8];
        xd[0] = pk2(xa.x, xa.x); xd[1] = pk2(xa.y, xa.y); xd[2] = pk2(xa.z, xa.z); xd[3] = pk2(xa.w, xa.w);
        xd[4] = pk2(xb.x, xb.x); xd[5] = pk2(xb.y, xb.y); xd[6] = pk2(xb.z, xb.z); xd[7] = pk2(xb.w, xb.w);
        ulonglong2 wA = *(const ulonglong2*)&wpair[c * 16 + 4 * w];
        ulonglong2 wB = *(const ulonglong2*)&wpair[c * 16 + 4 * w + 2];
#pragma unroll
        for (int j = 0; j < 8; j++) {
            acc[0][j] = fma2_(wA.x, xd[j], acc[0][j]);
            acc[1][j] = fma2_(wA.y, xd[j], acc[1][j]);
            acc[2][j] = fma2_(wB.x, xd[j], acc[2][j]);
            acc[3][j] = fma2_(wB.y, xd[j], acc[3][j]);
        }
    }
#pragma unroll
    for (int hp = 0; hp < 2; hp++) {
        const float* ah = attnsh + (2 * w + hp) * 16;
        u64 A0[4], A1[4];
#pragma unroll
        for (int e = 0; e < 4; e++) {
            A0[e] = pk2(ah[e], ah[4 + e]);
            A1[e] = pk2(ah[8 + e], ah[12 + e]);
        }
#pragma unroll
        for (int j = 0; j < 8; j++) {
            float v0, v1, v2, v3;
            upk2(acc[2 * hp][j], v0, v1);
            upk2(acc[2 * hp + 1][j], v2, v3);
            u64 vd0 = pk2(v0, v0), vd1 = pk2(v1, v1), vd2 = pk2(v2, v2), vd3 = pk2(v3, v3);
            u64 o01 = mul2_(A0[0], vd0);
            o01 = fma2_(A0[1], vd1, o01); o01 = fma2_(A0[2], vd2, o01); o01 = fma2_(A0[3], vd3, o01);
            u64 o23 = mul2_(A1[0], vd0);
            o23 = fma2_(A1[1], vd1, o23); o23 = fma2_(A1[2], vd2, o23); o23 = fma2_(A1[3], vd3, o23);
            acc[2 * hp][j] = o01;
            acc[2 * hp + 1][j] = o23;
        }
    }
    __syncthreads();
#pragma unroll
    for (int rp = 0; rp < 4; rp++) {
        float r0[8], r1[8];
#pragma unroll
        for (int j = 0; j < 8; j++) upk2(acc[rp][j], r0[j], r1[j]);
        int row0 = 8 * w + 2 * rp;
        *(float4*)(xsh + row0 * 256 + 4 * lane) = make_float4(r0[0], r0[1], r0[2], r0[3]);
        *(float4*)(xsh + row0 * 256 + 128 + 4 * lane) = make_float4(r0[4], r0[5], r0[6], r0[7]);
        *(float4*)(xsh + (row0 + 1) * 256 + 4 * lane) = make_float4(r1[0], r1[1], r1[2], r1[3]);
        *(float4*)(xsh + (row0 + 1) * 256 + 128 + 4 * lane) = make_float4(r1[4], r1[5], r1[6], r1[7]);
    }
    __syncthreads();
    u64 pa[4][8];
#pragma unroll
    for (int rp = 0; rp < 4; rp++) {
        u64 init = pk2(pbsh[8 * w + 2 * rp], pbsh[8 * w + 2 * rp + 1]);
#pragma unroll
        for (int j = 0; j < 8; j++) pa[rp][j] = init;
    }
#pragma unroll 4
    for (int jj = 0; jj < 32; jj++) {
        float4 ya = *(const float4*)(xsh + jj * 256 + 4 * lane);
        float4 yb = *(const float4*)(xsh + jj * 256 + 128 + 4 * lane);
        u64 yd[8];
        yd[0] = pk2(ya.x, ya.x); yd[1] = pk2(ya.y, ya.y); yd[2] = pk2(ya.z, ya.z); yd[3] = pk2(ya.w, ya.w);
        yd[4] = pk2(yb.x, yb.x); yd[5] = pk2(yb.y, yb.y); yd[6] = pk2(yb.z, yb.z); yd[7] = pk2(yb.w, yb.w);
        ulonglong2 wA = *(const ulonglong2*)&ppair[jj * 16 + 4 * w];
        ulonglong2 wB = *(const ulonglong2*)&ppair[jj * 16 + 4 * w + 2];
#pragma unroll
        for (int j = 0; j < 8; j++) {
            pa[0][j] = fma2_(wA.x, yd[j], pa[0][j]);
            pa[1][j] = fma2_(wA.y, yd[j], pa[1][j]);
            pa[2][j] = fma2_(wB.x, yd[j], pa[2][j]);
            pa[3][j] = fma2_(wB.y, yd[j], pa[3][j]);
        }
    }
    float* f2base = g_f2 + (size_t)b * CN * LN + l0b;
#pragma unroll
    for (int rp = 0; rp < 4; rp++) {
        float r0[8], r1[8];
#pragma unroll
        for (int j = 0; j < 8; j++) upk2(pa[rp][j], r0[j], r1[j]);
        int row0 = 8 * w + 2 * rp;
        *(float4*)(f2base + (size_t)row0 * LN + 4 * lane) = make_float4(r0[0], r0[1], r0[2], r0[3]);
        *(float4*)(f2base + (size_t)row0 * LN + 128 + 4 * lane) = make_float4(r0[4], r0[5], r0[6], r0[7]);
        *(float4*)(f2base + (size_t)(row0 + 1) * LN + 4 * lane) = make_float4(r1[0], r1[1], r1[2], r1[3]);
        *(float4*)(f2base + (size_t)(row0 + 1) * LN + 128 + 4 * lane) = make_float4(r1[4], r1[5], r1[6], r1[7]);
        float s0 = 0.f, m0 = -1e30f, s1 = 0.f, m1 = -1e30f;
#pragma unroll
        for (int j = 0; j < 8; j++) {
            s0 += r0[j]; m0 = fmaxf(m0, r0[j]);
            s1 += r1[j]; m1 = fmaxf(m1, r1[j]);
        }
#pragma unroll
        for (int off = 16; off > 0; off >>= 1) {
            s0 += __shfl_xor_sync(0xffffffffu, s0, off);
            m0 = fmaxf(m0, __shfl_xor_sync(0xffffffffu, m0, off));
            s1 += __shfl_xor_sync(0xffffffffu, s1, off);
            m1 = fmaxf(m1, __shfl_xor_sync(0xffffffffu, m1, off));
        }
        if (lane == 0) {
            size_t pbase = (size_t)(BN * NCH * 32) + ((size_t)b * NCH + ch) * 32;
            g_pf_sum[pbase + row0] = s0;     g_pf_max[pbase + row0] = m0;
            g_pf_sum[pbase + row0 + 1] = s1; g_pf_max[pbase + row0 + 1] = m1;
        }
    }
}

// ---------------- K5: channel MLPs + cross softmax (unchanged) ----------------
__global__ void k_cafm_vec(const float* __restrict__ a1w, const float* __restrict__ a1b,
                           const float* __restrict__ m1w, const float* __restrict__ m1b,
                           const float* __restrict__ a2w, const float* __restrict__ a2b,
                           const float* __restrict__ m2w, const float* __restrict__ m2b,
                           const float* __restrict__ a11w, const float* __restrict__ a11b,
                           const float* __restrict__ m11w, const float* __restrict__ m11b,
                           const float* __restrict__ a22w, const float* __restrict__ a22b,
                           const float* __restrict__ m22w, const float* __restrict__ m22b) {
    const int b = blockIdx.x, c = threadIdx.x;
    __shared__ float av1[32], mx1[32], av2[32], mx2[32];
    __shared__ float h1a[16], h1m[16], h2a[16], h2m[16];
    __shared__ float a1s[32], a2s[32];
    {
        float s1 = 0.f, m1 = -1e30f, s2 = 0.f, m2 = -1e30f;
        for (int chn = 0; chn < NCH; chn++) {
            s1 += g_pf_sum[((size_t)b * NCH + chn) * 32 + c];
            m1 = fmaxf(m1, g_pf_max[((size_t)b * NCH + chn) * 32 + c]);
            s2 += g_pf_sum[(size_t)(BN * NCH * 32) + ((size_t)b * NCH + chn) * 32 + c];
            m2 = fmaxf(m2, g_pf_max[(size_t)(BN * NCH * 32) + ((size_t)b * NCH + chn) * 32 + c]);
        }
        av1[c] = s1 * (1.f / LN); mx1[c] = m1;
        av2[c] = s2 * (1.f / LN); mx2[c] = m2;
    }
    __syncthreads();
    if (c < 16) {
        float s1 = a1b[c], s2 = m1b[c], s3 = a2b[c], s4 = m2b[c];
        for (int j = 0; j < 32; j++) {
            s1 += a1w[c * 32 + j] * av1[j];
            s2 += m1w[c * 32 + j] * mx1[j];
            s3 += a2w[c * 32 + j] * av2[j];
            s4 += m2w[c * 32 + j] * mx2[j];
        }
        h1a[c] = fmaxf(s1, 0.f); h1m[c] = fmaxf(s2, 0.f);
        h2a[c] = fmaxf(s3, 0.f); h2m[c] = fmaxf(s4, 0.f);
    }
    __syncthreads();
    {
        float s1 = a11b[c] + m11b[c];
        float s2 = a22b[c] + m22b[c];
        for (int j = 0; j < 16; j++) {
            s1 += a11w[c * 16 + j] * h1a[j] + m11w[c * 16 + j] * h1m[j];
            s2 += a22w[c * 16 + j] * h2a[j] + m22w[c * 16 + j] * h2m[j];
        }
        a1s[c] = s1; a2s[c] = s2;
    }
    __syncthreads();
    {
        float ac = a1s[c], m = -1e30f;
        for (int d = 0; d < 32; d++) m = fmaxf(m, ac * a2s[d]);
        float sum = 0.f;
        for (int d = 0; d < 32; d++) sum += expf(ac * a2s[d] - m);
        float inv = 1.f / sum;
        for (int d = 0; d < 32; d++) g_s1[(size_t)b * 1024 + c * 32 + d] = expf(ac * a2s[d] - m) * inv;
    }
    {
        float ac = a2s[c], m = -1e30f;
        for (int d = 0; d < 32; d++) m = fmaxf(m, ac * a1s[d]);
        float sum = 0.f;
        for (int d = 0; d < 32; d++) sum += expf(ac * a1s[d] - m);
        float inv = 1.f / sum;
        for (int d = 0; d < 32; d++) g_s2[(size_t)b * 1024 + c * 32 + d] = expf(ac * a1s[d] - m) * inv;
    }
}

// ---------------- K6: fused s@f + mean/max over C (R8-proven, unchanged) ----------------
__global__ __launch_bounds__(128) void k_gate_pool() {
    __shared__ __align__(16) u64 s1Td[1024];
    __shared__ __align__(16) u64 s2Td[1024];
    const int b = blockIdx.y, ch = blockIdx.x, tid = threadIdx.x;
    for (int i = tid; i < 1024; i += 128) {
        float a = g_s1[(size_t)b * 1024 + (i & 31) * 32 + (i >> 5)];
        s1Td[i] = pk2(a, a);
        float c2 = g_s2[(size_t)b * 1024 + (i & 31) * 32 + (i >> 5)];
        s2Td[i] = pk2(c2, c2);
    }
    __syncthreads();
    const int l0 = ch * CHK + 2 * tid;
    {
        u64 acc[32];
#pragma unroll
        for (int c = 0; c < 32; c++) acc[c] = 0ull;
#pragma unroll 4
        for (int d = 0; d < 32; d++) {
            u64 fd = *(const u64*)(g_f1 + (size_t)b * CN * LN + (size_t)d * LN + l0);
            const ulonglong2* sp = (const ulonglong2*)&s1Td[d * 32];
#pragma unroll
            for (int c2 = 0; c2 < 16; c2++) {
                ulonglong2 w = sp[c2];
                acc[2 * c2] = fma2_(w.x, fd, acc[2 * c2]);
                acc[2 * c2 + 1] = fma2_(w.y, fd, acc[2 * c2 + 1]);
            }
        }
        u64 sump = 0ull;
        float mx0 = -1e30f, mx1 = -1e30f;
#pragma unroll
        for (int c = 0; c < 32; c++) {
            sump = add2_(sump, acc[c]);
            float v0, v1; upk2(acc[c], v0, v1);
            mx0 = fmaxf(mx0, v0); mx1 = fmaxf(mx1, v1);
        }
        *(u64*)(g_pooled1 + (size_t)b * 2 * LN + l0) = mul2_(sump, pk2(1.f / 32.f, 1.f / 32.f));
        *(u64*)(g_pooled1 + (size_t)b * 2 * LN + LN + l0) = pk2(mx0, mx1);
    }
    {
        u64 acc[32];
#pragma unroll
        for (int c = 0; c < 32; c++) acc[c] = 0ull;
#pragma unroll 4
        for (int d = 0; d < 32; d++) {
            u64 fd = *(const u64*)(g_f2 + (size_t)b * CN * LN + (size_t)d * LN + l0);
            const ulonglong2* sp = (const ulonglong2*)&s2Td[d * 32];
#pragma unroll
            for (int c2 = 0; c2 < 16; c2++) {
                ulonglong2 w = sp[c2];
                acc[2 * c2] = fma2_(w.x, fd, acc[2 * c2]);
                acc[2 * c2 + 1] = fma2_(w.y, fd, acc[2 * c2 + 1]);
            }
        }
        u64 sump = 0ull;
        float mx0 = -1e30f, mx1 = -1e30f;
#pragma unroll
        for (int c = 0; c < 32; c++) {
            sump = add2_(sump, acc[c]);
            float v0, v1; upk2(acc[c], v0, v1);
            mx0 = fmaxf(mx0, v0); mx1 = fmaxf(mx1, v1);
        }
        *(u64*)(g_pooled2 + (size_t)b * 2 * LN + l0) = mul2_(sump, pk2(1.f / 32.f, 1.f / 32.f));
        *(u64*)(g_pooled2 + (size_t)b * 2 * LN + LN + l0) = pk2(mx0, mx1);
    }
}

// ---------------- K7: fused conv1 + conv2 + softmax stats (unchanged) ----------------
__global__ __launch_bounds__(256) void k_gate_conv(const float* __restrict__ c1w, const float* __restrict__ c1b,
                                                   const float* __restrict__ c2w, const float* __restrict__ c2b) {
    const int b = blockIdx.x, gate = blockIdx.y, tid = threadIdx.x;
    __shared__ float y1s[LN];
    __shared__ float red[256];
    const float* pin = (gate ? g_pooled2 : g_pooled1) + (size_t)b * 2 * LN;
    float* yo = (gate ? g_y2b : g_y2a) + (size_t)b * LN;
    float w1[18];
#pragma unroll
    for (int i = 0; i < 18; i++) w1[i] = c1w[i];
    float b1 = c1b[0];
    float w2[9];
#pragma unroll
    for (int i = 0; i < 9; i++) w2[i] = c2w[i];
    float b2 = c2b[0];
    for (int p = tid; p < LN; p += 256) {
        int hh = p / WN, ww = p % WN;
        float acc = b1;
#pragma unroll
        for (int ci = 0; ci < 2; ci++)
#pragma unroll
            for (int kh = 0; kh < 3; kh++) {
                int ih = hh + kh - 1;
                if (ih < 0 || ih >= HN) continue;
#pragma unroll
                for (int kw = 0; kw < 3; kw++) {
                    int iw = ww + kw - 1;
                    if (iw < 0 || iw >= WN) continue;
                    acc += pin[(size_t)ci * LN + ih * WN + iw] * w1[(ci * 3 + kh) * 3 + kw];
                }
            }
        y1s[p] = fmaxf(acc, 0.f);
    }
    __syncthreads();
    float yl[25];
    float mloc = -1e30f;
    int idx = 0;
    for (int p = tid; p < LN; p += 256, idx++) {
        int hh = p / WN, ww = p % WN;
        float acc = b2;
#pragma unroll
        for (int kh = 0; kh < 3; kh++) {
            int ih = hh + kh - 1;
            if (ih < 0 || ih >= HN) continue;
#pragma unroll
            for (int kw = 0; kw < 3; kw++) {
                int iw = ww + kw - 1;
                if (iw < 0 || iw >= WN) continue;
                acc += y1s[ih * WN + iw] * w2[kh * 3 + kw];
            }
        }
        yo[p] = acc;
        yl[idx] = acc;
        mloc = fmaxf(mloc, acc);
    }
    red[tid] = mloc;
    __syncthreads();
    for (int o = 128; o > 0; o >>= 1) { if (tid < o) red[tid] = fmaxf(red[tid], red[tid + o]); __syncthreads(); }
    float gm = red[0];
    __syncthreads();
    float sloc = 0.f;
#pragma unroll
    for (int i = 0; i < 25; i++) sloc += expf(yl[i] - gm);
    red[tid] = sloc;
    __syncthreads();
    for (int o = 128; o > 0; o >>= 1) { if (tid < o) red[tid] += red[tid + o]; __syncthreads(); }
    if (tid == 0) { g_gstat[(b * 2 + gate) * 2] = gm; g_gstat[(b * 2 + gate) * 2 + 1] = red[0]; }
}

// ---------------- K8: final gated residual combine (unchanged) ----------------
__global__ __launch_bounds__(256) void k_final(float* __restrict__ out) {
    const int NT4 = BN * CN * LN / 4;
    int i4 = blockIdx.x * 256 + threadIdx.x;
    if (i4 >= NT4) return;
    size_t i = (size_t)i4 * 4;
    int b = (int)(i / (CN * LN));
    int rem = (int)(i - (size_t)b * CN * LN);
    int l = rem % LN;
    float4 f1v = *(const float4*)(g_f1 + i);
    float4 f2v = *(const float4*)(g_f2 + i);
    float4 y1v = *(const float4*)(g_y2a + (size_t)b * LN + l);
    float4 y2v = *(const float4*)(g_y2b + (size_t)b * LN + l);
    float m1 = g_gstat[b * 4 + 0], s1i = 1.f / g_gstat[b * 4 + 1];
    float m2 = g_gstat[b * 4 + 2], s2i = 1.f / g_gstat[b * 4 + 3];
    float4 o;
    o.x = f1v.x * (1.f + expf(y1v.x - m1) * s1i) + f2v.x * (1.f + expf(y2v.x - m2) * s2i);
    o.y = f1v.y * (1.f + expf(y1v.y - m1) * s1i) + f2v.y * (1.f + expf(y2v.y - m2) * s2i);
    o.z = f1v.z * (1.f + expf(y1v.z - m1) * s1i) + f2v.z * (1.f + expf(y2v.z - m2) * s2i);
    o.w = f1v.w * (1.f + expf(y1v.w - m1) * s1i) + f2v.w * (1.f + expf(y2v.w - m2) * s2i);
    *(float4*)(out + i) = o;
}

// ---------------- launch ----------------
extern "C" void kernel_launch(void* const* d_in, const int* in_sizes, int n_in,
                              void* d_out, int out_size) {
    const float* rgb     = (const float*)d_in[0];
    const float* freq    = (const float*)d_in[1];
    const float* la_qkv  = (const float*)d_in[2];
    const float* la_pw   = (const float*)d_in[3];
    const float* la_pb   = (const float*)d_in[4];
    const float* la_dw   = (const float*)d_in[5];
    const float* xa_qkv  = (const float*)d_in[6];
    const float* xa_temp = (const float*)d_in[7];
    const float* xa_pw   = (const float*)d_in[8];
    const float* xa_pb   = (const float*)d_in[9];
    const float* c1w     = (const float*)d_in[10];
    const float* c1b     = (const float*)d_in[11];
    const float* c2w     = (const float*)d_in[12];
    const float* c2b     = (const float*)d_in[13];
    const float* avg1_w  = (const float*)d_in[14];
    const float* avg1_b  = (const float*)d_in[15];
    const float* max1_w  = (const float*)d_in[16];
    const float* max1_b  = (const float*)d_in[17];
    const float* avg2_w  = (const float*)d_in[18];
    const float* avg2_b  = (const float*)d_in[19];
    const float* max2_w  = (const float*)d_in[20];
    const float* max2_b  = (const float*)d_in[21];
    const float* avg11_w = (const float*)d_in[22];
    const float* avg11_b = (const float*)d_in[23];
    const float* max11_w = (const float*)d_in[24];
    const float* max11_b = (const float*)d_in[25];
    const float* avg22_w = (const float*)d_in[26];
    const float* avg22_b = (const float*)d_in[27];
    const float* max22_w = (const float*)d_in[28];
    const float* max22_b = (const float*)d_in[29];
    float* out = (float*)d_out;

    static int smem_set = 0;
    if (!smem_set) {
        cudaFuncSetAttribute(k_la_pass2, cudaFuncAttributeMaxDynamicSharedMemorySize, LA2_SMEM);
        cudaFuncSetAttribute(k_xca_pass2, cudaFuncAttributeMaxDynamicSharedMemorySize, XCA2_SMEM);
        smem_set = 1;
    }

    dim3 gBL(NCH, BN);
    k_la_pass1<<<gBL, 128>>>(rgb, la_qkv);
    k_xca_pass1<<<gBL, 128>>>(freq, xa_qkv);
    k_la_pass2<<<gBL, 128, LA2_SMEM>>>(rgb, la_qkv, la_pw, la_pb, la_dw);
    k_xca_pass2<<<gBL, 128, XCA2_SMEM>>>(freq, xa_qkv, xa_pw, xa_pb, xa_temp);
    k_cafm_vec<<<BN, 32>>>(avg1_w, avg1_b, max1_w, max1_b,
                           avg2_w, avg2_b, max2_w, max2_b,
                           avg11_w, avg11_b, max11_w, max11_b,
                           avg22_w, avg22_b, max22_w, max22_b);
    k_gate_pool<<<gBL, 128>>>();
    k_gate_conv<<<dim3(BN, 2), 256>>>(c1w, c1b, c2w, c2b);
    k_final<<<(BN * CN * LN / 4 + 255) / 256, 256>>>(out);
}